// round 7
// baseline (speedup 1.0000x reference)
#include <cuda_runtime.h>

// AUGRU: B=65536, T=50, E=10.
// r6 was ISSUE-bound (issue 71%, fma 40%, ~1200 instr/warp-step: every constant
// weight costs an explicit LDC on Blackwell). Fix: packed f32x2 — 2 rows/thread,
// fused weights stored as duplicated pairs in __constant__, one LDC.128 feeds
// two fma.rn.f32x2. ~2x fewer issue slots per row. Fused-weight live set
// (5 u64[10] arrays = 100 regs) + fenced LDC windows fits the 170-reg budget
// of __launch_bounds__(64,6) -- no spill (verify: DRAM% must stay low).

#define E_   10
#define T_   50
#define BTOT 65536
#define ROWS_PER_CTA 128
#define NTHR 64            // threads per CTA; each owns 2 rows
#define NPAIR 64
#define TC   2

typedef unsigned long long u64;

// Fused weights as duplicated pairs:
// cW4[m*50 + j*5 + kk] = (W'[2kk][j], W'[2kk][j], W'[2kk+1][j], W'[2kk+1][j])
// m: 0=Wi_r,1=Wh_r,2=Wi_z,3=Wh_z,4=Wi_h,5=Wh_h   (W' = W@Ws fused)
// cB2[m*10 + j] = (b'[j], b'[j])  m: 0=r,1=z,2=h
__device__   float4 gW4[300];
__device__   float2 gB2[30];
__constant__ float4 cW4[300];
__constant__ float2 cB2[30];

__global__ void prep_kernel(
    const float* __restrict__ WiR, const float* __restrict__ biR, const float* __restrict__ WhR,
    const float* __restrict__ WsR, const float* __restrict__ bsR,
    const float* __restrict__ WiZ, const float* __restrict__ biZ, const float* __restrict__ WhZ,
    const float* __restrict__ WsZ, const float* __restrict__ bsZ,
    const float* __restrict__ WiH, const float* __restrict__ biH, const float* __restrict__ WhH,
    const float* __restrict__ WtH, const float* __restrict__ btH)
{
    __shared__ float tmp[6][100];   // [m][j*10+k] = W'_m[k][j]
    const int t = threadIdx.x;
    const float* Am[6] = {WiR, WhR, WiZ, WhZ, WiH, WhH};
    const float* Bm[6] = {WsR, WsR, WsZ, WsZ, WtH, WtH};
    if (t < 100) {
        int j = t / E_;   // output col of fused W'
        int k = t % E_;   // input row
#pragma unroll
        for (int m = 0; m < 6; m++) {
            float s = 0.0f;
#pragma unroll
            for (int l = 0; l < E_; l++)
                s = fmaf(Am[m][k * E_ + l], Bm[m][l * E_ + j], s);
            tmp[m][j * E_ + k] = s;
        }
    }
    __syncthreads();
    if (t < 50) {
        int j = t / 5, kk = t % 5;
#pragma unroll
        for (int m = 0; m < 6; m++) {
            float w0 = tmp[m][j * E_ + 2 * kk];
            float w1 = tmp[m][j * E_ + 2 * kk + 1];
            gW4[m * 50 + j * 5 + kk] = make_float4(w0, w0, w1, w1);
        }
    }
    const float* bi[3] = {biR, biZ, biH};
    const float* bs[3] = {bsR, bsZ, btH};
    const float* Wo[3] = {WsR, WsZ, WtH};
    if (t < E_) {
#pragma unroll
        for (int m = 0; m < 3; m++) {
            float s = bs[m][t];
#pragma unroll
            for (int l = 0; l < E_; l++)
                s = fmaf(bi[m][l], Wo[m][l * E_ + t], s);
            gB2[m * E_ + t] = make_float2(s, s);
        }
    }
}

__device__ __forceinline__ u64 pk(float lo, float hi) {
    u64 r; asm("mov.b64 %0, {%1,%2};" : "=l"(r) : "f"(lo), "f"(hi)); return r;
}
__device__ __forceinline__ void upk(u64 v, float& lo, float& hi) {
    asm("mov.b64 {%0,%1}, %2;" : "=f"(lo), "=f"(hi) : "l"(v));
}
__device__ __forceinline__ u64 ffma2(u64 a, u64 b, u64 c) {
    u64 d; asm("fma.rn.f32x2 %0, %1, %2, %3;" : "=l"(d) : "l"(a), "l"(b), "l"(c)); return d;
}
__device__ __forceinline__ u64 fmul2(u64 a, u64 b) {
    u64 d; asm("mul.rn.f32x2 %0, %1, %2;" : "=l"(d) : "l"(a), "l"(b)); return d;
}
__device__ __forceinline__ u64 fadd2(u64 a, u64 b) {
    u64 d; asm("add.rn.f32x2 %0, %1, %2;" : "=l"(d) : "l"(a), "l"(b)); return d;
}
__device__ __forceinline__ u64 fsub2(u64 a, u64 b) {
    u64 d; asm("sub.rn.f32x2 %0, %1, %2;" : "=l"(d) : "l"(a), "l"(b)); return d;
}

// sigmoid / tanh, safe at extremes (exp->inf => rcp->0).
__device__ __forceinline__ float sigm(float v) {
    float e = __expf(-v);
    return __fdividef(1.0f, 1.0f + e);
}
__device__ __forceinline__ float tanh_f(float v) {
    float e = __expf(2.0f * v);
    return 1.0f - __fdividef(2.0f, 1.0f + e);
}
__device__ __forceinline__ u64 sigm2(u64 v) {
    float a, b; upk(v, a, b);
    return pk(sigm(a), sigm(b));
}

// acc[j] += dot(s, W'[:,j]) (pairwise), W' duplicated pairs in constant mem.
// Dual partial accumulators halve the dep chain; __syncwarp every 2 rows
// bounds ptxas's LDC batching window (anti-spill).
template <int OFF4>
__device__ __forceinline__ void mvc2(const u64* s, u64* acc) {
#pragma unroll
    for (int j = 0; j < E_; j++) {
        const ulonglong2* wr =
            reinterpret_cast<const ulonglong2*>(&cW4[OFF4 + j * 5]);
        ulonglong2 w0 = wr[0];
        u64 a = ffma2(s[0], w0.x, acc[j]);
        u64 b = fmul2(s[1], w0.y);
#pragma unroll
        for (int kk = 1; kk < 5; kk++) {
            ulonglong2 ww = wr[kk];
            a = ffma2(s[2 * kk],     ww.x, a);
            b = ffma2(s[2 * kk + 1], ww.y, b);
        }
        acc[j] = fadd2(a, b);
        if ((j & 1) == 1) __syncwarp();
    }
}

__global__ void __launch_bounds__(NTHR, 6) augru_kernel(
    const float* __restrict__ X, const float* __restrict__ A,
    const float* __restrict__ H0, float* __restrict__ Out)
{
    __shared__ __align__(16) float xsf[TC][E_][NPAIR][2];
    __shared__ __align__(16) float asf[TC][E_][NPAIR][2];

    const int tid = threadIdx.x;           // owns pair tid: rows 2*tid, 2*tid+1
    const int rowBase = blockIdx.x * ROWS_PER_CTA;

    // init h (broadcast h0)
    u64 h[E_];
#pragma unroll
    for (int e = 0; e < E_; e++) {
        float v = H0[e];
        h[e] = pk(v, v);
    }

    const u64* xs64 = reinterpret_cast<const u64*>(&xsf[0][0][0][0]);
    const u64* as64 = reinterpret_cast<const u64*>(&asf[0][0][0][0]);
    const float4* Xg = reinterpret_cast<const float4*>(X);
    const float4* Ag = reinterpret_cast<const float4*>(A);

#pragma unroll 1
    for (int t0 = 0; t0 < T_; t0 += TC) {
        __syncthreads();
        // ---- stage 2 steps of x,a for 128 rows (coalesced float4) ----
        // per row: 2*10 floats = 5 float4, contiguous. row stride = 125 float4.
        {
            const long cbase = (long)(t0 * E_) / 4;  // exact: t0 even
#pragma unroll
            for (int it = 0; it < 10; ++it) {
                int idx = it * NTHR + tid;           // 0..639
                int r = idx / 5, v = idx % 5;
                long g = (long)(rowBase + r) * 125 + cbase + v;
                float4 dx = Xg[g];
                float4 da = Ag[g];
                int p = r >> 1, hhalf = r & 1;
#pragma unroll
                for (int c = 0; c < 4; c++) {
                    int q = v * 4 + c;
                    int tl = (q >= E_) ? 1 : 0;
                    int e = q - E_ * tl;
                    float fx = (c == 0) ? dx.x : (c == 1) ? dx.y : (c == 2) ? dx.z : dx.w;
                    float fa = (c == 0) ? da.x : (c == 1) ? da.y : (c == 2) ? da.z : da.w;
                    xsf[tl][e][p][hhalf] = fx;
                    asf[tl][e][p][hhalf] = fa;
                }
            }
        }
        __syncthreads();

#pragma unroll 1
        for (int tt = 0; tt < TC; ++tt) {
            u64 x[E_];
#pragma unroll
            for (int e = 0; e < E_; e++)
                x[e] = xs64[(tt * E_ + e) * NPAIR + tid];

            u64 acc[E_], r[E_], hz[E_];

            // ---------------- z gate (fused) ----------------
#pragma unroll
            for (int j = 0; j < E_; j++)
                acc[j] = *reinterpret_cast<const u64*>(&cB2[E_ + j]);
            mvc2<100>(x, acc);   // x @ Wi_z'
            mvc2<150>(h, acc);   // h @ Wh_z'
#pragma unroll
            for (int j = 0; j < E_; j++)
                hz[j] = fmul2(h[j], sigm2(acc[j]));

            // ---------------- r gate (fused) ----------------
#pragma unroll
            for (int j = 0; j < E_; j++)
                acc[j] = *reinterpret_cast<const u64*>(&cB2[j]);
            mvc2<0>(x, acc);     // x @ Wi_r'
            mvc2<50>(h, acc);    // h @ Wh_r'
#pragma unroll
            for (int j = 0; j < E_; j++)
                r[j] = sigm2(acc[j]);

            // ---------------- candidate (fused) ----------------
#pragma unroll
            for (int j = 0; j < E_; j++)
                acc[j] = *reinterpret_cast<const u64*>(&cB2[2 * E_ + j]);
            mvc2<200>(x, acc);   // x dead after this
            mvc2<250>(hz, acc);  // hz dead after this

            // ---------------- h update ----------------
#pragma unroll
            for (int e = 0; e < E_; e++) {
                float c0, c1;
                upk(acc[e], c0, c1);
                u64 c  = pk(tanh_f(c0), tanh_f(c1));
                u64 Ra = fmul2(as64[(tt * E_ + e) * NPAIR + tid], r[e]);
                h[e] = ffma2(Ra, fsub2(c, h[e]), h[e]);
            }
        }
    }

    // ---- store final h: rows 2*tid, 2*tid+1 ----
    const long r0 = (long)(rowBase + 2 * tid) * E_;
#pragma unroll
    for (int e = 0; e < E_; e++) {
        float a, b;
        upk(h[e], a, b);
        Out[r0 + e]      = a;
        Out[r0 + E_ + e] = b;
    }
}

extern "C" void kernel_launch(void* const* d_in, const int* in_sizes, int n_in,
                              void* d_out, int out_size) {
    const float* X   = (const float*)d_in[0];
    const float* A   = (const float*)d_in[1];
    const float* H0  = (const float*)d_in[2];
    const float* WiR = (const float*)d_in[3];
    const float* biR = (const float*)d_in[4];
    const float* WhR = (const float*)d_in[5];
    const float* WsR = (const float*)d_in[6];
    const float* bsR = (const float*)d_in[7];
    const float* WiZ = (const float*)d_in[8];
    const float* biZ = (const float*)d_in[9];
    const float* WhZ = (const float*)d_in[10];
    const float* WsZ = (const float*)d_in[11];
    const float* bsZ = (const float*)d_in[12];
    const float* WiH = (const float*)d_in[13];
    const float* biH = (const float*)d_in[14];
    const float* WhH = (const float*)d_in[15];
    const float* WtH = (const float*)d_in[16];
    const float* btH = (const float*)d_in[17];
    float* Out = (float*)d_out;

    prep_kernel<<<1, 128>>>(WiR, biR, WhR, WsR, bsR,
                            WiZ, biZ, WhZ, WsZ, bsZ,
                            WiH, biH, WhH, WtH, btH);

    // fused dup-pair params -> constant bank (D2D, graph-capturable)
    void* gw = nullptr; void* gb = nullptr;
    cudaGetSymbolAddress(&gw, gW4);
    cudaGetSymbolAddress(&gb, gB2);
    cudaMemcpyToSymbolAsync(cW4, gw, 300 * sizeof(float4), 0,
                            cudaMemcpyDeviceToDevice, 0);
    cudaMemcpyToSymbolAsync(cB2, gb, 30 * sizeof(float2), 0,
                            cudaMemcpyDeviceToDevice, 0);

    dim3 grid(BTOT / ROWS_PER_CTA);  // 512
    dim3 block(NTHR);                // 64
    augru_kernel<<<grid, block>>>(X, A, H0, Out);
}

// round 8
// speedup vs baseline: 1.0061x; 1.0061x over previous
#include <cuda_runtime.h>

// AUGRU: B=65536, T=50, E=10.
// r7 (f32x2 + __constant__) was const-port bound: LDC.128->GPR runs at ~16cyc/
// SMSP (half-rate GPR const port) -> 300 loads/warp-step = ~4800cyc, matching
// the 242us measurement. This round keeps the f32x2 instruction halving but
// serves the duplicated weight pairs from SHARED memory: warp-uniform LDS.128
// is a broadcast (N=1, structural floor 2/SMSP) -> ~8x cheaper per load.
// Weights: prep_kernel fuses (x@Wi+bi+h@Wh)@Ws+bs -> x@Wi' + h@Wh' + b' and
// writes dup-pairs to __device__ globals; each CTA copies 4.8KB into shared.

#define E_   10
#define T_   50
#define BTOT 65536
#define ROWS_PER_CTA 128
#define NTHR 64            // threads per CTA; each owns 2 rows
#define NPAIR 64
#define TC   2

typedef unsigned long long u64;

// Fused weights as duplicated pairs:
// gW4[m*50 + j*5 + kk] = (W'[2kk][j], W'[2kk][j], W'[2kk+1][j], W'[2kk+1][j])
// m: 0=Wi_r,1=Wh_r,2=Wi_z,3=Wh_z,4=Wi_h,5=Wh_h   (W' = W@Ws fused)
// gB2[m*10 + j] = (b'[j], b'[j])  m: 0=r,1=z,2=h
__device__ float4 gW4[300];
__device__ float2 gB2[30];

__global__ void prep_kernel(
    const float* __restrict__ WiR, const float* __restrict__ biR, const float* __restrict__ WhR,
    const float* __restrict__ WsR, const float* __restrict__ bsR,
    const float* __restrict__ WiZ, const float* __restrict__ biZ, const float* __restrict__ WhZ,
    const float* __restrict__ WsZ, const float* __restrict__ bsZ,
    const float* __restrict__ WiH, const float* __restrict__ biH, const float* __restrict__ WhH,
    const float* __restrict__ WtH, const float* __restrict__ btH)
{
    __shared__ float tmp[6][100];   // [m][j*10+k] = W'_m[k][j]
    const int t = threadIdx.x;
    const float* Am[6] = {WiR, WhR, WiZ, WhZ, WiH, WhH};
    const float* Bm[6] = {WsR, WsR, WsZ, WsZ, WtH, WtH};
    if (t < 100) {
        int j = t / E_;   // output col of fused W'
        int k = t % E_;   // input row
#pragma unroll
        for (int m = 0; m < 6; m++) {
            float s = 0.0f;
#pragma unroll
            for (int l = 0; l < E_; l++)
                s = fmaf(Am[m][k * E_ + l], Bm[m][l * E_ + j], s);
            tmp[m][j * E_ + k] = s;
        }
    }
    __syncthreads();
    if (t < 50) {
        int j = t / 5, kk = t % 5;
#pragma unroll
        for (int m = 0; m < 6; m++) {
            float w0 = tmp[m][j * E_ + 2 * kk];
            float w1 = tmp[m][j * E_ + 2 * kk + 1];
            gW4[m * 50 + j * 5 + kk] = make_float4(w0, w0, w1, w1);
        }
    }
    const float* bi[3] = {biR, biZ, biH};
    const float* bs[3] = {bsR, bsZ, btH};
    const float* Wo[3] = {WsR, WsZ, WtH};
    if (t < E_) {
#pragma unroll
        for (int m = 0; m < 3; m++) {
            float s = bs[m][t];
#pragma unroll
            for (int l = 0; l < E_; l++)
                s = fmaf(bi[m][l], Wo[m][l * E_ + t], s);
            gB2[m * E_ + t] = make_float2(s, s);
        }
    }
}

__device__ __forceinline__ u64 pk(float lo, float hi) {
    u64 r; asm("mov.b64 %0, {%1,%2};" : "=l"(r) : "f"(lo), "f"(hi)); return r;
}
__device__ __forceinline__ void upk(u64 v, float& lo, float& hi) {
    asm("mov.b64 {%0,%1}, %2;" : "=f"(lo), "=f"(hi) : "l"(v));
}
__device__ __forceinline__ u64 ffma2(u64 a, u64 b, u64 c) {
    u64 d; asm("fma.rn.f32x2 %0, %1, %2, %3;" : "=l"(d) : "l"(a), "l"(b), "l"(c)); return d;
}
__device__ __forceinline__ u64 fmul2(u64 a, u64 b) {
    u64 d; asm("mul.rn.f32x2 %0, %1, %2;" : "=l"(d) : "l"(a), "l"(b)); return d;
}
__device__ __forceinline__ u64 fadd2(u64 a, u64 b) {
    u64 d; asm("add.rn.f32x2 %0, %1, %2;" : "=l"(d) : "l"(a), "l"(b)); return d;
}
__device__ __forceinline__ u64 fsub2(u64 a, u64 b) {
    u64 d; asm("sub.rn.f32x2 %0, %1, %2;" : "=l"(d) : "l"(a), "l"(b)); return d;
}

// sigmoid / tanh, safe at extremes (exp->inf => rcp->0).
__device__ __forceinline__ float sigm(float v) {
    float e = __expf(-v);
    return __fdividef(1.0f, 1.0f + e);
}
__device__ __forceinline__ float tanh_f(float v) {
    float e = __expf(2.0f * v);
    return 1.0f - __fdividef(2.0f, 1.0f + e);
}
__device__ __forceinline__ u64 sigm2(u64 v) {
    float a, b; upk(v, a, b);
    return pk(sigm(a), sigm(b));
}

// acc[j] += dot(s, W'[:,j]) (pairwise); w = dup-pair weights in SHARED.
// All lanes read the same address -> LDS.128 broadcast (no conflict).
// Dual partial accumulators halve the dep chain; __syncwarp every 2 rows
// bounds ptxas's load-batching window (anti-spill, kept from r7: regs=165).
__device__ __forceinline__ void mv2(const ulonglong2* __restrict__ w,
                                    const u64* s, u64* acc) {
#pragma unroll
    for (int j = 0; j < E_; j++) {
        const ulonglong2* wr = w + j * 5;
        ulonglong2 w0 = wr[0];
        u64 a = ffma2(s[0], w0.x, acc[j]);
        u64 b = fmul2(s[1], w0.y);
#pragma unroll
        for (int kk = 1; kk < 5; kk++) {
            ulonglong2 ww = wr[kk];
            a = ffma2(s[2 * kk],     ww.x, a);
            b = ffma2(s[2 * kk + 1], ww.y, b);
        }
        acc[j] = fadd2(a, b);
        if ((j & 1) == 1) __syncwarp();
    }
}

__global__ void __launch_bounds__(NTHR, 6) augru_kernel(
    const float* __restrict__ X, const float* __restrict__ A,
    const float* __restrict__ H0, float* __restrict__ Out)
{
    __shared__ __align__(16) ulonglong2 sW[300];  // dup-pair fused weights
    __shared__ __align__(16) u64        sB[30];   // dup fused biases
    __shared__ __align__(16) float xsf[TC][E_][NPAIR][2];
    __shared__ __align__(16) float asf[TC][E_][NPAIR][2];

    const int tid = threadIdx.x;           // owns pair tid: rows 2*tid, 2*tid+1
    const int rowBase = blockIdx.x * ROWS_PER_CTA;

    // ---- copy fused weights/biases into shared (4.8KB + 240B) ----
    {
        const float4* gw = gW4;
#pragma unroll
        for (int i = tid; i < 300; i += NTHR) {
            float4 v = __ldg(&gw[i]);
            sW[i] = *reinterpret_cast<const ulonglong2*>(&v);
        }
        if (tid < 30) {
            float2 v = __ldg(&gB2[tid]);
            sB[tid] = *reinterpret_cast<const u64*>(&v);
        }
    }

    // init h (broadcast h0)
    u64 h[E_];
#pragma unroll
    for (int e = 0; e < E_; e++) {
        float v = H0[e];
        h[e] = pk(v, v);
    }

    const u64* xs64 = reinterpret_cast<const u64*>(&xsf[0][0][0][0]);
    const u64* as64 = reinterpret_cast<const u64*>(&asf[0][0][0][0]);
    const float4* Xg = reinterpret_cast<const float4*>(X);
    const float4* Ag = reinterpret_cast<const float4*>(A);

#pragma unroll 1
    for (int t0 = 0; t0 < T_; t0 += TC) {
        __syncthreads();
        // ---- stage 2 steps of x,a for 128 rows (coalesced float4) ----
        // per row: 2*10 floats = 5 float4, contiguous. row stride = 125 float4.
        {
            const long cbase = (long)(t0 * E_) / 4;  // exact: t0 even
#pragma unroll
            for (int it = 0; it < 10; ++it) {
                int idx = it * NTHR + tid;           // 0..639
                int r = idx / 5, v = idx % 5;
                long g = (long)(rowBase + r) * 125 + cbase + v;
                float4 dx = Xg[g];
                float4 da = Ag[g];
                int p = r >> 1, hhalf = r & 1;
#pragma unroll
                for (int c = 0; c < 4; c++) {
                    int q = v * 4 + c;
                    int tl = (q >= E_) ? 1 : 0;
                    int e = q - E_ * tl;
                    float fx = (c == 0) ? dx.x : (c == 1) ? dx.y : (c == 2) ? dx.z : dx.w;
                    float fa = (c == 0) ? da.x : (c == 1) ? da.y : (c == 2) ? da.z : da.w;
                    xsf[tl][e][p][hhalf] = fx;
                    asf[tl][e][p][hhalf] = fa;
                }
            }
        }
        __syncthreads();

#pragma unroll 1
        for (int tt = 0; tt < TC; ++tt) {
            u64 x[E_];
#pragma unroll
            for (int e = 0; e < E_; e++)
                x[e] = xs64[(tt * E_ + e) * NPAIR + tid];

            u64 acc[E_], r[E_], hz[E_];

            // ---------------- z gate (fused) ----------------
#pragma unroll
            for (int j = 0; j < E_; j++) acc[j] = sB[E_ + j];
            mv2(sW + 100, x, acc);   // x @ Wi_z'
            mv2(sW + 150, h, acc);   // h @ Wh_z'
#pragma unroll
            for (int j = 0; j < E_; j++)
                hz[j] = fmul2(h[j], sigm2(acc[j]));

            // ---------------- r gate (fused) ----------------
#pragma unroll
            for (int j = 0; j < E_; j++) acc[j] = sB[j];
            mv2(sW, x, acc);         // x @ Wi_r'
            mv2(sW + 50, h, acc);    // h @ Wh_r'
#pragma unroll
            for (int j = 0; j < E_; j++)
                r[j] = sigm2(acc[j]);

            // ---------------- candidate (fused) ----------------
#pragma unroll
            for (int j = 0; j < E_; j++) acc[j] = sB[2 * E_ + j];
            mv2(sW + 200, x, acc);   // x dead after this
            mv2(sW + 250, hz, acc);  // hz dead after this

            // ---------------- h update ----------------
#pragma unroll
            for (int e = 0; e < E_; e++) {
                float c0, c1;
                upk(acc[e], c0, c1);
                u64 c  = pk(tanh_f(c0), tanh_f(c1));
                u64 Ra = fmul2(as64[(tt * E_ + e) * NPAIR + tid], r[e]);
                h[e] = ffma2(Ra, fsub2(c, h[e]), h[e]);
            }
        }
    }

    // ---- store final h: rows 2*tid, 2*tid+1 ----
    const long r0 = (long)(rowBase + 2 * tid) * E_;
#pragma unroll
    for (int e = 0; e < E_; e++) {
        float a, b;
        upk(h[e], a, b);
        Out[r0 + e]      = a;
        Out[r0 + E_ + e] = b;
    }
}

extern "C" void kernel_launch(void* const* d_in, const int* in_sizes, int n_in,
                              void* d_out, int out_size) {
    const float* X   = (const float*)d_in[0];
    const float* A   = (const float*)d_in[1];
    const float* H0  = (const float*)d_in[2];
    const float* WiR = (const float*)d_in[3];
    const float* biR = (const float*)d_in[4];
    const float* WhR = (const float*)d_in[5];
    const float* WsR = (const float*)d_in[6];
    const float* bsR = (const float*)d_in[7];
    const float* WiZ = (const float*)d_in[8];
    const float* biZ = (const float*)d_in[9];
    const float* WhZ = (const float*)d_in[10];
    const float* WsZ = (const float*)d_in[11];
    const float* bsZ = (const float*)d_in[12];
    const float* WiH = (const float*)d_in[13];
    const float* biH = (const float*)d_in[14];
    const float* WhH = (const float*)d_in[15];
    const float* WtH = (const float*)d_in[16];
    const float* btH = (const float*)d_in[17];
    float* Out = (float*)d_out;

    prep_kernel<<<1, 128>>>(WiR, biR, WhR, WsR, bsR,
                            WiZ, biZ, WhZ, WsZ, bsZ,
                            WiH, biH, WhH, WtH, btH);

    dim3 grid(BTOT / ROWS_PER_CTA);  // 512
    dim3 block(NTHR);                // 64
    augru_kernel<<<grid, block>>>(X, A, H0, Out);
}

// round 10
// speedup vs baseline: 1.1332x; 1.1263x over previous
#include <cuda_runtime.h>

// AUGRU: B=65536, T=50, E=10.
// (Resubmission of r9 — previous bench died on a container infra failure,
//  producing no evidence; theory unchanged.)
// Lesson history: weight operands MUST ride the uniform-constant path
// (LDCU, floor 1, separate port; FFMA takes UR operand directly).
//   r6: scalar 1 row/thread, __constant__ -> 170us (issue-bound 71%).
//   r7: f32x2 via LDC.128->GPR: half-rate const port -> 247us.
//   r8: f32x2 via LDS.128 "broadcast": 512B crossbar cost -> 247us, L1 67%.
// This round: scalar LDCU path, but TWO rows per thread so each constant
// load feeds two FMAs -> ~23% fewer issue slots per row, 2x ILP per thread.

#define E_   10
#define T_   50
#define BTOT 65536
#define ROWS_PER_CTA 128
#define NTHR 64            // threads per CTA; each owns rows 2*tid, 2*tid+1
#define NPAIR 64
#define TC   2

// Flat fused parameter block (scalar):
//  [m*100 + j*10 + k] = W'_m[k][j]  (transposed), m: 0=Wi_r,1=Wh_r,2=Wi_z,3=Wh_z,4=Wi_h,5=Wh_h
//  [600 + m*10 + j]   = fused bias, m: 0=r,1=z,2=h
#define PSZ (6 * 100 + 3 * E_)
__device__   float gAll[PSZ];
__constant__ float cAll[PSZ];

__global__ void prep_kernel(
    const float* __restrict__ WiR, const float* __restrict__ biR, const float* __restrict__ WhR,
    const float* __restrict__ WsR, const float* __restrict__ bsR,
    const float* __restrict__ WiZ, const float* __restrict__ biZ, const float* __restrict__ WhZ,
    const float* __restrict__ WsZ, const float* __restrict__ bsZ,
    const float* __restrict__ WiH, const float* __restrict__ biH, const float* __restrict__ WhH,
    const float* __restrict__ WtH, const float* __restrict__ btH)
{
    const int t = threadIdx.x;
    const float* Am[6] = {WiR, WhR, WiZ, WhZ, WiH, WhH};
    const float* Bm[6] = {WsR, WsR, WsZ, WsZ, WtH, WtH};
    if (t < 100) {
        int j = t / E_;   // output col of fused W'
        int k = t % E_;   // input row
#pragma unroll
        for (int m = 0; m < 6; m++) {
            float s = 0.0f;
#pragma unroll
            for (int l = 0; l < E_; l++)
                s = fmaf(Am[m][k * E_ + l], Bm[m][l * E_ + j], s);
            gAll[m * 100 + j * E_ + k] = s;   // transposed store
        }
    }
    const float* bi[3] = {biR, biZ, biH};
    const float* bs[3] = {bsR, bsZ, btH};
    const float* Wo[3] = {WsR, WsZ, WtH};
    if (t < E_) {
#pragma unroll
        for (int m = 0; m < 3; m++) {
            float s = bs[m][t];
#pragma unroll
            for (int l = 0; l < E_; l++)
                s = fmaf(bi[m][l], Wo[m][l * E_ + t], s);
            gAll[600 + m * E_ + t] = s;
        }
    }
}

// sigmoid / tanh, safe at extremes (exp->inf => rcp->0).
__device__ __forceinline__ float sigm(float v) {
    float e = __expf(-v);
    return __fdividef(1.0f, 1.0f + e);
}
__device__ __forceinline__ float tanh_f(float v) {
    float e = __expf(2.0f * v);
    return 1.0f - __fdividef(2.0f, 1.0f + e);
}

// Dual-row matvec: acc{0,1}[j] += dot(s{0,1}, W'[:,j]); W' in __constant__ at
// literal offsets -> LDCU (uniform port), each constant feeds 2 FMAs.
// __syncwarp every 5 output rows bounds the load-batching window (anti-spill).
template <int OFF>
__device__ __forceinline__ void mvc2r(const float* s0, const float* s1,
                                      float* a0, float* a1) {
#pragma unroll
    for (int j = 0; j < E_; j++) {
        float p0 = a0[j], p1 = a1[j];
#pragma unroll
        for (int k = 0; k < E_; k++) {
            float w = cAll[OFF + j * E_ + k];
            p0 = fmaf(s0[k], w, p0);
            p1 = fmaf(s1[k], w, p1);
        }
        a0[j] = p0; a1[j] = p1;
        if (j == 4) __syncwarp();
    }
    __syncwarp();
}

__global__ void __launch_bounds__(NTHR, 6) augru_kernel(
    const float* __restrict__ X, const float* __restrict__ A,
    const float* __restrict__ H0, float* __restrict__ Out)
{
    __shared__ __align__(16) float xsf[TC][E_][NPAIR][2];
    __shared__ __align__(16) float asf[TC][E_][NPAIR][2];

    const int tid = threadIdx.x;           // owns rows 2*tid, 2*tid+1
    const int rowBase = blockIdx.x * ROWS_PER_CTA;

    // init h (broadcast h0)
    float h0[E_], h1[E_];
#pragma unroll
    for (int e = 0; e < E_; e++) {
        float v = H0[e];
        h0[e] = v; h1[e] = v;
    }

    const float2* xs2 = reinterpret_cast<const float2*>(&xsf[0][0][0][0]);
    const float2* as2 = reinterpret_cast<const float2*>(&asf[0][0][0][0]);
    const float4* Xg = reinterpret_cast<const float4*>(X);
    const float4* Ag = reinterpret_cast<const float4*>(A);

#pragma unroll 1
    for (int t0 = 0; t0 < T_; t0 += TC) {
        __syncthreads();
        // ---- stage 2 steps of x,a for 128 rows (coalesced float4) ----
        // per row: 2*10 floats = 5 float4, contiguous. row stride = 125 float4.
        {
            const long cbase = (long)(t0 * E_) / 4;  // exact: t0 even
#pragma unroll
            for (int it = 0; it < 10; ++it) {
                int idx = it * NTHR + tid;           // 0..639
                int r = idx / 5, v = idx % 5;
                long g = (long)(rowBase + r) * 125 + cbase + v;
                float4 dx = Xg[g];
                float4 da = Ag[g];
                int p = r >> 1, hhalf = r & 1;
#pragma unroll
                for (int c = 0; c < 4; c++) {
                    int q = v * 4 + c;
                    int tl = (q >= E_) ? 1 : 0;
                    int e = q - E_ * tl;
                    float fx = (c == 0) ? dx.x : (c == 1) ? dx.y : (c == 2) ? dx.z : dx.w;
                    float fa = (c == 0) ? da.x : (c == 1) ? da.y : (c == 2) ? da.z : da.w;
                    xsf[tl][e][p][hhalf] = fx;
                    asf[tl][e][p][hhalf] = fa;
                }
            }
        }
        __syncthreads();

#pragma unroll 1
        for (int tt = 0; tt < TC; ++tt) {
            float x0[E_], x1[E_];
#pragma unroll
            for (int e = 0; e < E_; e++) {
                float2 xv = xs2[(tt * E_ + e) * NPAIR + tid];
                x0[e] = xv.x; x1[e] = xv.y;
            }

            float a0[E_], a1[E_], r0[E_], r1[E_], hz0[E_], hz1[E_];

            // ---------------- z gate (fused) ----------------
#pragma unroll
            for (int j = 0; j < E_; j++) {
                float b = cAll[600 + E_ + j];
                a0[j] = b; a1[j] = b;
            }
            mvc2r<200>(x0, x1, a0, a1);   // x @ Wi_z'
            mvc2r<300>(h0, h1, a0, a1);   // h @ Wh_z'
#pragma unroll
            for (int j = 0; j < E_; j++) {
                hz0[j] = h0[j] * sigm(a0[j]);
                hz1[j] = h1[j] * sigm(a1[j]);
            }

            // ---------------- r gate (fused) ----------------
#pragma unroll
            for (int j = 0; j < E_; j++) {
                float b = cAll[600 + j];
                a0[j] = b; a1[j] = b;
            }
            mvc2r<0>(x0, x1, a0, a1);     // x @ Wi_r'
            mvc2r<100>(h0, h1, a0, a1);   // h @ Wh_r'
#pragma unroll
            for (int j = 0; j < E_; j++) {
                r0[j] = sigm(a0[j]);
                r1[j] = sigm(a1[j]);
            }

            // ---------------- candidate (fused) ----------------
#pragma unroll
            for (int j = 0; j < E_; j++) {
                float b = cAll[600 + 2 * E_ + j];
                a0[j] = b; a1[j] = b;
            }
            mvc2r<400>(x0, x1, a0, a1);   // x dead after this
            mvc2r<500>(hz0, hz1, a0, a1); // hz dead after this

            // ---------------- h update ----------------
#pragma unroll
            for (int e = 0; e < E_; e++) {
                float2 av = as2[(tt * E_ + e) * NPAIR + tid];
                float c0 = tanh_f(a0[e]);
                float c1 = tanh_f(a1[e]);
                float Ra0 = av.x * r0[e];
                float Ra1 = av.y * r1[e];
                h0[e] += Ra0 * (c0 - h0[e]);
                h1[e] += Ra1 * (c1 - h1[e]);
            }
        }
    }

    // ---- store final h: rows 2*tid, 2*tid+1 (20 contiguous floats, 16B-aligned) ----
    {
        float buf[2 * E_];
#pragma unroll
        for (int e = 0; e < E_; e++) { buf[e] = h0[e]; buf[E_ + e] = h1[e]; }
        float4* o4 = reinterpret_cast<float4*>(Out + (long)(rowBase + 2 * tid) * E_);
#pragma unroll
        for (int i = 0; i < 5; i++)
            o4[i] = reinterpret_cast<const float4*>(buf)[i];
    }
}

extern "C" void kernel_launch(void* const* d_in, const int* in_sizes, int n_in,
                              void* d_out, int out_size) {
    const float* X   = (const float*)d_in[0];
    const float* A   = (const float*)d_in[1];
    const float* H0  = (const float*)d_in[2];
    const float* WiR = (const float*)d_in[3];
    const float* biR = (const float*)d_in[4];
    const float* WhR = (const float*)d_in[5];
    const float* WsR = (const float*)d_in[6];
    const float* bsR = (const float*)d_in[7];
    const float* WiZ = (const float*)d_in[8];
    const float* biZ = (const float*)d_in[9];
    const float* WhZ = (const float*)d_in[10];
    const float* WsZ = (const float*)d_in[11];
    const float* bsZ = (const float*)d_in[12];
    const float* WiH = (const float*)d_in[13];
    const float* biH = (const float*)d_in[14];
    const float* WhH = (const float*)d_in[15];
    const float* WtH = (const float*)d_in[16];
    const float* btH = (const float*)d_in[17];
    float* Out = (float*)d_out;

    prep_kernel<<<1, 128>>>(WiR, biR, WhR, WsR, bsR,
                            WiZ, biZ, WhZ, WsZ, bsZ,
                            WiH, biH, WhH, WtH, btH);

    // fused params -> constant bank (D2D memcpy, graph-capturable)
    void* gsym = nullptr;
    cudaGetSymbolAddress(&gsym, gAll);
    cudaMemcpyToSymbolAsync(cAll, gsym, PSZ * sizeof(float), 0,
                            cudaMemcpyDeviceToDevice, 0);

    dim3 grid(BTOT / ROWS_PER_CTA);  // 512
    dim3 block(NTHR);                // 64
    augru_kernel<<<grid, block>>>(X, A, H0, Out);
}